// round 12
// baseline (speedup 1.0000x reference)
#include <cuda_runtime.h>
#include <cuda_fp16.h>
#include <cstdint>
#include <math.h>

#define N_TOK 8192
#define C_DIM 128
#define D_DIM 64

#define BM 64
#define BN 64
#define NTILES (N_TOK / BN)

// ===========================================================================
// Globals (allocation-free scratch), all fp16
// ===========================================================================
__device__ __half g_q [N_TOK * D_DIM];   // [n][d], pre-scaled by log2e/8
__device__ __half g_k [N_TOK * D_DIM];   // [n][d]
__device__ __half g_vT[D_DIM * N_TOK];   // [d][n]

// ===========================================================================
// PTX helpers (base-ISA only)
// ===========================================================================
__device__ __forceinline__ uint32_t smem_u32(const void* p) {
    uint32_t a;
    asm("{ .reg .u64 t; cvta.to.shared.u64 t, %1; cvt.u32.u64 %0, t; }"
        : "=r"(a) : "l"(p));
    return a;
}
#define CP16(dst, src) \
    asm volatile("cp.async.cg.shared.global [%0], [%1], 16;" \
        :: "r"(dst), "l"(src))
#define CP_COMMIT() asm volatile("cp.async.commit_group;")
#define CP_WAIT1()  asm volatile("cp.async.wait_group 1;" ::: "memory")
#define BAR_GRP(id) \
    asm volatile("bar.sync %0, 64;" :: "r"(id) : "memory")

#define LDSM4(r, addr) \
    asm volatile("ldmatrix.sync.aligned.m8n8.x4.shared.b16 {%0,%1,%2,%3}, [%4];" \
        : "=r"((r)[0]), "=r"((r)[1]), "=r"((r)[2]), "=r"((r)[3]) : "r"(addr))

__device__ __forceinline__ void mma16816(float d[4], const uint32_t a[4],
                                         const uint32_t b[2]) {
    asm volatile(
        "mma.sync.aligned.m16n8k16.row.col.f32.f16.f16.f32 "
        "{%0,%1,%2,%3}, {%4,%5,%6,%7}, {%8,%9}, {%0,%1,%2,%3};"
        : "+f"(d[0]), "+f"(d[1]), "+f"(d[2]), "+f"(d[3])
        : "r"(a[0]), "r"(a[1]), "r"(a[2]), "r"(a[3]), "r"(b[0]), "r"(b[1]));
}

// packs: result.lo = f16(a), result.hi = f16(b)
#define CVT_F16X2(result, a, b) \
    asm("cvt.rn.f16x2.f32 %0, %1, %2;" : "=r"(result) : "f"(b), "f"(a))
// fp32 MUFU exp2 (scores pre-scaled by log2e)
#define EX2(r, x) asm("ex2.approx.f32 %0, %1;" : "=f"(r) : "f"(x))

// ===========================================================================
// Kernel 1: transpose-gather + QKV projection (fp32, W in smem) + fp16 out.
// 128 blocks x 512 threads. V transposed through padded smem -> coalesced.
// ===========================================================================
#define VS_STRIDE 72     // halfs per row (64 + 8 pad)
#define QKV_X    24576                   // float offset of x tile
#define QKV_VS   (QKV_X + 8192)          // float offset of v staging
#define QKV_SMEM (QKV_VS * 4 + 64 * VS_STRIDE * 2)   // 140288 bytes

__global__ __launch_bounds__(512) void qkv_kernel(
    const float* __restrict__ hid,
    const float* __restrict__ wq,
    const float* __restrict__ wk,
    const float* __restrict__ wv)
{
    extern __shared__ float dsm[];
    float* wsq = dsm;                 // 8192 floats
    float* wsk = dsm + 8192;
    float* wsv = dsm + 16384;
    float* xs  = dsm + QKV_X;         // [128][64]
    __half* vsh = (__half*)(dsm + QKV_VS);               // [64][VS_STRIDE]

    const int tid = threadIdx.x;
    const int n0  = blockIdx.x * 64;
    const int bt  = n0 >> 8;
    const int hw0 = n0 & 255;
    const float* base = hid + (size_t)bt * (C_DIM * 256) + hw0;

    #pragma unroll
    for (int i = 0; i < 4; i++) {
        int id = tid + i * 512;
        ((float4*)wsq)[id] = ((const float4*)wq)[id];
        ((float4*)wsk)[id] = ((const float4*)wk)[id];
        ((float4*)wsv)[id] = ((const float4*)wv)[id];
    }
    #pragma unroll
    for (int i = 0; i < 4; i++) {
        int idx = tid + i * 512;
        int c = idx >> 4, r4 = idx & 15;
        *(float4*)&xs[c * 64 + r4 * 4] = *(const float4*)(base + c * 256 + r4 * 4);
    }
    __syncthreads();

    const int col = tid & 63;
    const int rg  = tid >> 6;                 // 0..7 -> rows rg*8..rg*8+7

    float aq[8], ak[8], av[8];
    #pragma unroll
    for (int u = 0; u < 8; u++) { aq[u] = 0.f; ak[u] = 0.f; av[u] = 0.f; }

    #pragma unroll 8
    for (int c = 0; c < C_DIM; c++) {
        float wqv = wsq[c * 64 + col];
        float wkv = wsk[c * 64 + col];
        float wvv = wsv[c * 64 + col];
        float4 x0 = *(const float4*)&xs[c * 64 + rg * 8];
        float4 x1 = *(const float4*)&xs[c * 64 + rg * 8 + 4];
        float xv[8] = {x0.x, x0.y, x0.z, x0.w, x1.x, x1.y, x1.z, x1.w};
        #pragma unroll
        for (int u = 0; u < 8; u++) {
            aq[u] = fmaf(xv[u], wqv, aq[u]);
            ak[u] = fmaf(xv[u], wkv, ak[u]);
            av[u] = fmaf(xv[u], wvv, av[u]);
        }
    }

    #pragma unroll
    for (int u = 0; u < 8; u++) {
        int n = n0 + rg * 8 + u;
        g_q[n * 64 + col] = __float2half(aq[u] * 0.1803368801f);  // /8 * log2e
        g_k[n * 64 + col] = __float2half(ak[u]);
        vsh[col * VS_STRIDE + rg * 8 + u] = __float2half(av[u]);
    }
    __syncthreads();

    {
        int d  = tid >> 3;
        int ch = tid & 7;
        uint4 hi = *(uint4*)&vsh[d * VS_STRIDE + ch * 8];
        *(uint4*)((char*)g_vT + (size_t)d * 16384 + n0 * 2 + ch * 16) = hi;
    }
}

// ===========================================================================
// Kernel 2: flash attention on mma.sync, all fp16, B-fragment reuse,
// half-tile S waves (reduced live registers).
// 128 CTAs x 256 threads; FOUR decoupled 64-thread groups (2 warps each),
// group g -> tiles t = g, g+4, ...; 2-slot private rings.
// Each warp owns 32 rows (2 m-fragments) -> every LDSM feeds 2 MMAs.
// ===========================================================================
#define SM_Q   0
#define SM_KV  8192
#define KVBUF  16384            // k 0 | v 8192
#define SMEM_TOTAL (SM_KV + 8 * KVBUF)    // 139264 bytes

// per-group prefetch: 64 threads, one 16KB tile-set
__device__ __forceinline__ void prefetch_tile(uint32_t kvbuf, int t, int lt)
{
    #pragma unroll
    for (int i = 0; i < 8; i++) {
        int id = lt + i * 64;
        int row = id >> 3;
        int ch  = (id & 7) * 16;
        uint32_t sw = (uint32_t)row * 128 + (uint32_t)(ch ^ ((row & 7) << 4));
        CP16(kvbuf +         sw, (const char*)g_k  + t * 8192 + row * 128 + ch);
        CP16(kvbuf + 8192 + sw, (const char*)g_vT + (size_t)row * 16384 + t * 128 + ch);
    }
}

// exp + pack for local block j of the current S half; key-group kk = base2+(j>>1)
#define SOFTMAX_ONE(S, PHI, RSA, RSB, j, base2) do {                          \
    float e0, e1, e2, e3;                                                     \
    EX2(e0, S[j][0]); EX2(e1, S[j][1]);                                       \
    EX2(e2, S[j][2]); EX2(e3, S[j][3]);                                       \
    RSA += e0 + e1;                                                           \
    RSB += e2 + e3;                                                           \
    const int kk = (base2) + ((j) >> 1), u = ((j) & 1) * 2;                   \
    CVT_F16X2(PHI[kk][u],     e0, e1);                                        \
    CVT_F16X2(PHI[kk][u + 1], e2, e3);                                        \
} while (0)

// S for key-column blocks colbase..colbase+3 into s0/s1[0..3] (32 keys)
#define S_HALF(colbase) do {                                                  \
    uint32_t B[4][8];                                                         \
    _Pragma("unroll")                                                         \
    for (int j = 0; j < 4; j++) {                                             \
        uint32_t rb = kv + (uint32_t)((colbase) + j) * 1024 + browB;          \
        LDSM4(&B[j][0], rb + cA);                                             \
        LDSM4(&B[j][4], rb + cB);                                             \
    }                                                                         \
    _Pragma("unroll")                                                         \
    for (int ks = 0; ks < 4; ks++)                                            \
        _Pragma("unroll")                                                     \
        for (int j = 0; j < 4; j++) {                                         \
            mma16816(s0[j], qf[0][ks], &B[j][ks * 2]);                        \
            mma16816(s1[j], qf[1][ks], &B[j][ks * 2]);                        \
        }                                                                     \
} while (0)

// PV quarter: output blocks base..base+3, key-half via COFF, P-frags PA/PB
#define PV_QTR(base, COFF, PA, PB) do {                                       \
    uint32_t B[4][4];                                                         \
    _Pragma("unroll")                                                         \
    for (int j = 0; j < 4; j++) {                                             \
        uint32_t rb = kv + 8192 + (uint32_t)((base) + j) * 1024 + browB;      \
        LDSM4(&B[j][0], rb + (COFF));                                         \
    }                                                                         \
    _Pragma("unroll")                                                         \
    for (int j = 0; j < 4; j++) {                                             \
        mma16816(o0[(base) + j], phi0[PA], &B[j][0]);                         \
        mma16816(o1[(base) + j], phi1[PA], &B[j][0]);                         \
    }                                                                         \
    _Pragma("unroll")                                                         \
    for (int j = 0; j < 4; j++) {                                             \
        mma16816(o0[(base) + j], phi0[PB], &B[j][2]);                         \
        mma16816(o1[(base) + j], phi1[PB], &B[j][2]);                         \
    }                                                                         \
} while (0)

__global__ __launch_bounds__(256, 1) void attn_mma(float* __restrict__ out)
{
    extern __shared__ char sm[];
    const uint32_t sb = smem_u32(sm);
    const int tid  = threadIdx.x;
    const int lane = tid & 31;
    const int wid  = tid >> 5;        // 0..7
    const int grp  = wid >> 1;        // 0..3: tiles t = grp mod 4
    const int wg   = wid & 1;         // warp-in-group: rows wg*32..wg*32+31
    const int lt   = tid & 63;        // thread id within group
    const int m0   = blockIdx.x * BM;

    // ---- stage Q tile (swizzled), all 256 threads ----
    {
        const char* qg = (const char*)g_q + m0 * 128;   // 64 rows x 128B
        int row = tid >> 2;
        int ch  = (tid & 3) * 32;      // 2 x 16B per thread
        uint32_t sw0 = (uint32_t)row * 128 + (uint32_t)((ch)      ^ ((row & 7) << 4));
        uint32_t sw1 = (uint32_t)row * 128 + (uint32_t)((ch + 16) ^ ((row & 7) << 4));
        *(uint4*)(sm + SM_Q + sw0) = *(const uint4*)(qg + row * 128 + ch);
        *(uint4*)(sm + SM_Q + sw1) = *(const uint4*)(qg + row * 128 + ch + 16);
    }

    // prologue: each group prefetches its first two tiles into its 2 slots
    const uint32_t ring = sb + SM_KV + (uint32_t)grp * 2 * KVBUF;
    prefetch_tile(ring,         grp,     lt);
    CP_COMMIT();
    prefetch_tile(ring + KVBUF, grp + 4, lt);
    CP_COMMIT();
    __syncthreads();

    // ---- Q A-fragments: 2 m-fragments (32 rows) per warp ----
    uint32_t qf[2][4][4];
    {
        uint32_t cxor = (uint32_t)(lane & 7) << 4;
        #pragma unroll
        for (int m = 0; m < 2; m++) {
            int qrow = wg * 32 + m * 16 + (lane & 15);
            uint32_t qbase = sb + SM_Q + (uint32_t)qrow * 128;
            #pragma unroll
            for (int ks = 0; ks < 4; ks++) {
                uint32_t ch = (uint32_t)(ks * 32 + ((lane >> 4) << 4));
                LDSM4(qf[m][ks], qbase + (ch ^ cxor));
            }
        }
    }

    float o0[8][4], o1[8][4];
    #pragma unroll
    for (int nt = 0; nt < 8; nt++)
        #pragma unroll
        for (int j = 0; j < 4; j++) { o0[nt][j] = 0.f; o1[nt][j] = 0.f; }
    float rs[4] = {0.f, 0.f, 0.f, 0.f};   // {m0.rowA, m0.rowB, m1.rowA, m1.rowB}

    const uint32_t browB = (uint32_t)(lane & 7) * 128;
    const uint32_t cA = (uint32_t)((((lane >> 3) & 3) << 4) ^ ((lane & 7) << 4));
    const uint32_t cB = cA ^ 64u;
    const int barid = grp + 1;

    int slot = 0;
    for (int t = grp; t < NTILES; t += 4, slot ^= 1) {
        const uint32_t kv = ring + (uint32_t)slot * KVBUF;

        CP_WAIT1();            // this slot's cp.async complete
        BAR_GRP(barid);        // whole group sees the data

        float s0[4][4], s1[4][4];
        uint32_t phi0[4][4], phi1[4][4];

        // ---- first half: S keys 0-31 ----
        #pragma unroll
        for (int j = 0; j < 4; j++)
            #pragma unroll
            for (int c = 0; c < 4; c++) { s0[j][c] = 0.f; s1[j][c] = 0.f; }
        S_HALF(0);
        SOFTMAX_ONE(s0, phi0, rs[0], rs[1], 0, 0); SOFTMAX_ONE(s1, phi1, rs[2], rs[3], 0, 0);
        SOFTMAX_ONE(s0, phi0, rs[0], rs[1], 1, 0); SOFTMAX_ONE(s1, phi1, rs[2], rs[3], 1, 0);
        SOFTMAX_ONE(s0, phi0, rs[0], rs[1], 2, 0); SOFTMAX_ONE(s1, phi1, rs[2], rs[3], 2, 0);
        SOFTMAX_ONE(s0, phi0, rs[0], rs[1], 3, 0); SOFTMAX_ONE(s1, phi1, rs[2], rs[3], 3, 0);

        // ---- second half: S keys 32-63 (reuse s regs) ----
        #pragma unroll
        for (int j = 0; j < 4; j++)
            #pragma unroll
            for (int c = 0; c < 4; c++) { s0[j][c] = 0.f; s1[j][c] = 0.f; }
        S_HALF(4);

        // ---- PV keys 0-31 (phi[0,1]) || exp/pack of second half ----
        PV_QTR(0, cA, 0, 1);
        SOFTMAX_ONE(s0, phi0, rs[0], rs[1], 0, 2); SOFTMAX_ONE(s1, phi1, rs[2], rs[3], 0, 2);
        SOFTMAX_ONE(s0, phi0, rs[0], rs[1], 1, 2); SOFTMAX_ONE(s1, phi1, rs[2], rs[3], 1, 2);
        PV_QTR(4, cA, 0, 1);
        SOFTMAX_ONE(s0, phi0, rs[0], rs[1], 2, 2); SOFTMAX_ONE(s1, phi1, rs[2], rs[3], 2, 2);
        SOFTMAX_ONE(s0, phi0, rs[0], rs[1], 3, 2); SOFTMAX_ONE(s1, phi1, rs[2], rs[3], 3, 2);

        // ---- PV keys 32-63 (phi[2,3]) ----
        PV_QTR(0, cB, 2, 3);
        PV_QTR(4, cB, 2, 3);

        BAR_GRP(barid);        // group done reading this slot
        if (t + 8 < NTILES)
            prefetch_tile(kv, t + 8, lt);   // refill the slot just consumed
        CP_COMMIT();           // keep wait_group counting uniform
    }

    // ---- combine the four groups (reuse KV smem as scratch) ----
    __syncthreads();
    float* sc = (float*)(sm + SM_KV);     // 3 x 64 threads x 68 floats
    if (grp > 0) {
        float* d = sc + ((grp - 1) * 64 + lt) * 68;
        #pragma unroll
        for (int nt = 0; nt < 8; nt++) {
            #pragma unroll
            for (int j = 0; j < 4; j++) {
                d[nt * 4 + j]      = o0[nt][j];
                d[32 + nt * 4 + j] = o1[nt][j];
            }
        }
        d[64] = rs[0]; d[65] = rs[1]; d[66] = rs[2]; d[67] = rs[3];
    }
    __syncthreads();
    if (grp == 0) {
        #pragma unroll
        for (int g = 0; g < 3; g++) {
            const float* d = sc + (g * 64 + lt) * 68;
            #pragma unroll
            for (int nt = 0; nt < 8; nt++) {
                #pragma unroll
                for (int j = 0; j < 4; j++) {
                    o0[nt][j] += d[nt * 4 + j];
                    o1[nt][j] += d[32 + nt * 4 + j];
                }
            }
            rs[0] += d[64]; rs[1] += d[65]; rs[2] += d[66]; rs[3] += d[67];
        }

        #pragma unroll
        for (int r = 0; r < 4; r++) {
            rs[r] += __shfl_xor_sync(0xffffffffu, rs[r], 1);
            rs[r] += __shfl_xor_sync(0xffffffffu, rs[r], 2);
        }
        const float inv[4] = {1.f / rs[0], 1.f / rs[1], 1.f / rs[2], 1.f / rs[3]};

        const int r0 = lane >> 2;
        const int c0 = (lane & 3) * 2;
        #pragma unroll
        for (int m = 0; m < 2; m++) {
            const int mrow = m0 + wg * 32 + m * 16 + r0;
            const float ia = inv[m * 2], ib = inv[m * 2 + 1];
            #pragma unroll
            for (int nt = 0; nt < 8; nt++) {
                const float* oo = m ? o1[nt] : o0[nt];
                float2 v0 = make_float2(oo[0] * ia, oo[1] * ia);
                float2 v1 = make_float2(oo[2] * ib, oo[3] * ib);
                *(float2*)(out + (size_t)mrow * 64 + nt * 8 + c0)       = v0;
                *(float2*)(out + (size_t)(mrow + 8) * 64 + nt * 8 + c0) = v1;
            }
        }
    }
}

// ===========================================================================
extern "C" void kernel_launch(void* const* d_in, const int* in_sizes, int n_in,
                              void* d_out, int out_size)
{
    const float* hid = (const float*)d_in[0];
    const float* wq  = (const float*)d_in[1];
    const float* wk  = (const float*)d_in[2];
    const float* wv  = (const float*)d_in[3];
    float* out = (float*)d_out;

    cudaFuncSetAttribute(qkv_kernel,
                         cudaFuncAttributeMaxDynamicSharedMemorySize, QKV_SMEM);
    cudaFuncSetAttribute(attn_mma,
                         cudaFuncAttributeMaxDynamicSharedMemorySize, SMEM_TOTAL);

    qkv_kernel<<<N_TOK / 64, 512, QKV_SMEM>>>(hid, wq, wk, wv);
    attn_mma<<<N_TOK / BM, 256, SMEM_TOTAL>>>(out);
}

// round 13
// speedup vs baseline: 1.0368x; 1.0368x over previous
#include <cuda_runtime.h>
#include <cuda_fp16.h>
#include <cstdint>
#include <math.h>

#define N_TOK 8192
#define C_DIM 128
#define D_DIM 64

#define BM 64
#define BN 64
#define NTILES (N_TOK / BN)

// ===========================================================================
// Globals (allocation-free scratch), all fp16
// ===========================================================================
__device__ __half g_q [N_TOK * D_DIM];   // [n][d], pre-scaled by log2e/8
__device__ __half g_k [N_TOK * D_DIM];   // [n][d]
__device__ __half g_vT[D_DIM * N_TOK];   // [d][n]

// ===========================================================================
// PTX helpers (base-ISA only)
// ===========================================================================
__device__ __forceinline__ uint32_t smem_u32(const void* p) {
    uint32_t a;
    asm("{ .reg .u64 t; cvta.to.shared.u64 t, %1; cvt.u32.u64 %0, t; }"
        : "=r"(a) : "l"(p));
    return a;
}
#define CP16(dst, src) \
    asm volatile("cp.async.cg.shared.global [%0], [%1], 16;" \
        :: "r"(dst), "l"(src))
#define CP_COMMIT() asm volatile("cp.async.commit_group;")
#define CP_WAIT1()  asm volatile("cp.async.wait_group 1;" ::: "memory")
#define BAR_GRP(id) \
    asm volatile("bar.sync %0, 64;" :: "r"(id) : "memory")

#define LDSM4(r, addr) \
    asm volatile("ldmatrix.sync.aligned.m8n8.x4.shared.b16 {%0,%1,%2,%3}, [%4];" \
        : "=r"((r)[0]), "=r"((r)[1]), "=r"((r)[2]), "=r"((r)[3]) : "r"(addr))

__device__ __forceinline__ void mma16816(float d[4], const uint32_t a[4],
                                         const uint32_t b[2]) {
    asm volatile(
        "mma.sync.aligned.m16n8k16.row.col.f32.f16.f16.f32 "
        "{%0,%1,%2,%3}, {%4,%5,%6,%7}, {%8,%9}, {%0,%1,%2,%3};"
        : "+f"(d[0]), "+f"(d[1]), "+f"(d[2]), "+f"(d[3])
        : "r"(a[0]), "r"(a[1]), "r"(a[2]), "r"(a[3]), "r"(b[0]), "r"(b[1]));
}

// packs: result.lo = f16(a), result.hi = f16(b)
#define CVT_F16X2(result, a, b) \
    asm("cvt.rn.f16x2.f32 %0, %1, %2;" : "=r"(result) : "f"(b), "f"(a))
// packed fp16x2 exp2 (scores pre-scaled by log2e)
#define HEX2(r, x) asm("ex2.approx.f16x2 %0, %1;" : "=r"(r) : "r"(x))

// ===========================================================================
// Kernel 1: transpose-gather + QKV projection (fp32, W in smem) + fp16 out.
// 128 blocks x 512 threads. V transposed through padded smem -> coalesced.
// ===========================================================================
#define VS_STRIDE 72     // halfs per row (64 + 8 pad)
#define QKV_X    24576                   // float offset of x tile
#define QKV_VS   (QKV_X + 8192)          // float offset of v staging
#define QKV_SMEM (QKV_VS * 4 + 64 * VS_STRIDE * 2)   // 140288 bytes

__global__ __launch_bounds__(512) void qkv_kernel(
    const float* __restrict__ hid,
    const float* __restrict__ wq,
    const float* __restrict__ wk,
    const float* __restrict__ wv)
{
    extern __shared__ float dsm[];
    float* wsq = dsm;                 // 8192 floats
    float* wsk = dsm + 8192;
    float* wsv = dsm + 16384;
    float* xs  = dsm + QKV_X;         // [128][64]
    __half* vsh = (__half*)(dsm + QKV_VS);               // [64][VS_STRIDE]

    const int tid = threadIdx.x;
    const int n0  = blockIdx.x * 64;
    const int bt  = n0 >> 8;
    const int hw0 = n0 & 255;
    const float* base = hid + (size_t)bt * (C_DIM * 256) + hw0;

    #pragma unroll
    for (int i = 0; i < 4; i++) {
        int id = tid + i * 512;
        ((float4*)wsq)[id] = ((const float4*)wq)[id];
        ((float4*)wsk)[id] = ((const float4*)wk)[id];
        ((float4*)wsv)[id] = ((const float4*)wv)[id];
    }
    #pragma unroll
    for (int i = 0; i < 4; i++) {
        int idx = tid + i * 512;
        int c = idx >> 4, r4 = idx & 15;
        *(float4*)&xs[c * 64 + r4 * 4] = *(const float4*)(base + c * 256 + r4 * 4);
    }
    __syncthreads();

    const int col = tid & 63;
    const int rg  = tid >> 6;                 // 0..7 -> rows rg*8..rg*8+7

    float aq[8], ak[8], av[8];
    #pragma unroll
    for (int u = 0; u < 8; u++) { aq[u] = 0.f; ak[u] = 0.f; av[u] = 0.f; }

    #pragma unroll 8
    for (int c = 0; c < C_DIM; c++) {
        float wqv = wsq[c * 64 + col];
        float wkv = wsk[c * 64 + col];
        float wvv = wsv[c * 64 + col];
        float4 x0 = *(const float4*)&xs[c * 64 + rg * 8];
        float4 x1 = *(const float4*)&xs[c * 64 + rg * 8 + 4];
        float xv[8] = {x0.x, x0.y, x0.z, x0.w, x1.x, x1.y, x1.z, x1.w};
        #pragma unroll
        for (int u = 0; u < 8; u++) {
            aq[u] = fmaf(xv[u], wqv, aq[u]);
            ak[u] = fmaf(xv[u], wkv, ak[u]);
            av[u] = fmaf(xv[u], wvv, av[u]);
        }
    }

    #pragma unroll
    for (int u = 0; u < 8; u++) {
        int n = n0 + rg * 8 + u;
        g_q[n * 64 + col] = __float2half(aq[u] * 0.1803368801f);  // /8 * log2e
        g_k[n * 64 + col] = __float2half(ak[u]);
        vsh[col * VS_STRIDE + rg * 8 + u] = __float2half(av[u]);
    }
    __syncthreads();

    {
        int d  = tid >> 3;
        int ch = tid & 7;
        uint4 hi = *(uint4*)&vsh[d * VS_STRIDE + ch * 8];
        *(uint4*)((char*)g_vT + (size_t)d * 16384 + n0 * 2 + ch * 16) = hi;
    }
}

// ===========================================================================
// Kernel 2: flash attention on mma.sync, all fp16, B-fragment reuse,
// packed-f16x2 exp + row-sums via ones-column MMA.
// 128 CTAs x 256 threads; FOUR decoupled 64-thread groups (2 warps each),
// group g -> tiles t = g, g+4, ...; 2-slot private rings.
// ===========================================================================
#define SM_Q   0
#define SM_KV  8192
#define KVBUF  16384            // k 0 | v 8192
#define SMEM_TOTAL (SM_KV + 8 * KVBUF)    // 139264 bytes

// per-group prefetch: 64 threads, one 16KB tile-set
__device__ __forceinline__ void prefetch_tile(uint32_t kvbuf, int t, int lt)
{
    #pragma unroll
    for (int i = 0; i < 8; i++) {
        int id = lt + i * 64;
        int row = id >> 3;
        int ch  = (id & 7) * 16;
        uint32_t sw = (uint32_t)row * 128 + (uint32_t)(ch ^ ((row & 7) << 4));
        CP16(kvbuf +         sw, (const char*)g_k  + t * 8192 + row * 128 + ch);
        CP16(kvbuf + 8192 + sw, (const char*)g_vT + (size_t)row * 16384 + t * 128 + ch);
    }
}

// pack score pairs to fp16x2, then packed exp2 -> phi directly
#define SOFTMAX_ONE(S, PHI, nt) do {                                          \
    uint32_t p01, p23;                                                        \
    CVT_F16X2(p01, S[nt][0], S[nt][1]);                                       \
    CVT_F16X2(p23, S[nt][2], S[nt][3]);                                       \
    const int kk = (nt) >> 1, u = ((nt) & 1) * 2;                             \
    HEX2(PHI[kk][u],     p01);                                                \
    HEX2(PHI[kk][u + 1], p23);                                                \
} while (0)

// S for nt = base..base+3, BOTH m-fragments reuse each B-fragment
#define S_HALF(base) do {                                                     \
    uint32_t B[4][8];                                                         \
    _Pragma("unroll")                                                         \
    for (int j = 0; j < 4; j++) {                                             \
        uint32_t rb = kv + (uint32_t)((base) + j) * 1024 + browB;             \
        LDSM4(&B[j][0], rb + cA);                                             \
        LDSM4(&B[j][4], rb + cB);                                             \
    }                                                                         \
    _Pragma("unroll")                                                         \
    for (int ks = 0; ks < 4; ks++)                                            \
        _Pragma("unroll")                                                     \
        for (int j = 0; j < 4; j++) {                                         \
            mma16816(s0[(base) + j], qf[0][ks], &B[j][ks * 2]);               \
            mma16816(s1[(base) + j], qf[1][ks], &B[j][ks * 2]);               \
        }                                                                     \
} while (0)

// PV quarter: both m-fragments reuse each V B-fragment
#define PV_QTR(base, COFF, PA, PB) do {                                       \
    uint32_t B[4][4];                                                         \
    _Pragma("unroll")                                                         \
    for (int j = 0; j < 4; j++) {                                             \
        uint32_t rb = kv + 8192 + (uint32_t)((base) + j) * 1024 + browB;      \
        LDSM4(&B[j][0], rb + (COFF));                                         \
    }                                                                         \
    _Pragma("unroll")                                                         \
    for (int j = 0; j < 4; j++) {                                             \
        mma16816(o0[(base) + j], phi0[PA], &B[j][0]);                         \
        mma16816(o1[(base) + j], phi1[PA], &B[j][0]);                         \
    }                                                                         \
    _Pragma("unroll")                                                         \
    for (int j = 0; j < 4; j++) {                                             \
        mma16816(o0[(base) + j], phi0[PB], &B[j][2]);                         \
        mma16816(o1[(base) + j], phi1[PB], &B[j][2]);                         \
    }                                                                         \
} while (0)

__global__ __launch_bounds__(256, 1) void attn_mma(float* __restrict__ out)
{
    extern __shared__ char sm[];
    const uint32_t sb = smem_u32(sm);
    const int tid  = threadIdx.x;
    const int lane = tid & 31;
    const int wid  = tid >> 5;        // 0..7
    const int grp  = wid >> 1;        // 0..3: tiles t = grp mod 4
    const int wg   = wid & 1;         // warp-in-group: rows wg*32..wg*32+31
    const int lt   = tid & 63;        // thread id within group
    const int m0   = blockIdx.x * BM;

    // ---- stage Q tile (swizzled), all 256 threads ----
    {
        const char* qg = (const char*)g_q + m0 * 128;   // 64 rows x 128B
        int row = tid >> 2;
        int ch  = (tid & 3) * 32;      // 2 x 16B per thread
        uint32_t sw0 = (uint32_t)row * 128 + (uint32_t)((ch)      ^ ((row & 7) << 4));
        uint32_t sw1 = (uint32_t)row * 128 + (uint32_t)((ch + 16) ^ ((row & 7) << 4));
        *(uint4*)(sm + SM_Q + sw0) = *(const uint4*)(qg + row * 128 + ch);
        *(uint4*)(sm + SM_Q + sw1) = *(const uint4*)(qg + row * 128 + ch + 16);
    }

    // prologue: each group prefetches its first two tiles into its 2 slots
    const uint32_t ring = sb + SM_KV + (uint32_t)grp * 2 * KVBUF;
    prefetch_tile(ring,         grp,     lt);
    CP_COMMIT();
    prefetch_tile(ring + KVBUF, grp + 4, lt);
    CP_COMMIT();
    __syncthreads();

    // ---- Q A-fragments: 2 m-fragments (32 rows) per warp ----
    uint32_t qf[2][4][4];
    {
        uint32_t cxor = (uint32_t)(lane & 7) << 4;
        #pragma unroll
        for (int m = 0; m < 2; m++) {
            int qrow = wg * 32 + m * 16 + (lane & 15);
            uint32_t qbase = sb + SM_Q + (uint32_t)qrow * 128;
            #pragma unroll
            for (int ks = 0; ks < 4; ks++) {
                uint32_t ch = (uint32_t)(ks * 32 + ((lane >> 4) << 4));
                LDSM4(qf[m][ks], qbase + (ch ^ cxor));
            }
        }
    }

    float o0[8][4], o1[8][4];
    #pragma unroll
    for (int nt = 0; nt < 8; nt++)
        #pragma unroll
        for (int j = 0; j < 4; j++) { o0[nt][j] = 0.f; o1[nt][j] = 0.f; }
    // row-sum accumulators (ones-column MMA); d[0]=rowA sum, d[2]=rowB sum
    float os0[4] = {0.f, 0.f, 0.f, 0.f};
    float os1[4] = {0.f, 0.f, 0.f, 0.f};
    const uint32_t onesb[2] = {0x3C003C00u, 0x3C003C00u};   // fp16 1.0 x4

    const uint32_t browB = (uint32_t)(lane & 7) * 128;
    const uint32_t cA = (uint32_t)((((lane >> 3) & 3) << 4) ^ ((lane & 7) << 4));
    const uint32_t cB = cA ^ 64u;
    const int barid = grp + 1;

    int slot = 0;
    for (int t = grp; t < NTILES; t += 4, slot ^= 1) {
        const uint32_t kv = ring + (uint32_t)slot * KVBUF;

        CP_WAIT1();            // this slot's cp.async complete
        BAR_GRP(barid);        // whole group sees the data

        float s0[8][4], s1[8][4];
        #pragma unroll
        for (int nt = 0; nt < 8; nt++)
            #pragma unroll
            for (int j = 0; j < 4; j++) { s0[nt][j] = 0.f; s1[nt][j] = 0.f; }

        uint32_t phi0[4][4], phi1[4][4];

        S_HALF(0);
        S_HALF(4);
        SOFTMAX_ONE(s0, phi0, 0); SOFTMAX_ONE(s1, phi1, 0);
        SOFTMAX_ONE(s0, phi0, 1); SOFTMAX_ONE(s1, phi1, 1);
        SOFTMAX_ONE(s0, phi0, 2); SOFTMAX_ONE(s1, phi1, 2);
        SOFTMAX_ONE(s0, phi0, 3); SOFTMAX_ONE(s1, phi1, 3);
        // row sums for keys 0-31 (phi[0,1])
        mma16816(os0, phi0[0], onesb); mma16816(os1, phi1[0], onesb);
        mma16816(os0, phi0[1], onesb); mma16816(os1, phi1[1], onesb);
        PV_QTR(0, cA, 0, 1);
        SOFTMAX_ONE(s0, phi0, 4); SOFTMAX_ONE(s1, phi1, 4);
        SOFTMAX_ONE(s0, phi0, 5); SOFTMAX_ONE(s1, phi1, 5);
        SOFTMAX_ONE(s0, phi0, 6); SOFTMAX_ONE(s1, phi1, 6);
        SOFTMAX_ONE(s0, phi0, 7); SOFTMAX_ONE(s1, phi1, 7);
        // row sums for keys 32-63 (phi[2,3])
        mma16816(os0, phi0[2], onesb); mma16816(os1, phi1[2], onesb);
        mma16816(os0, phi0[3], onesb); mma16816(os1, phi1[3], onesb);
        PV_QTR(4, cA, 0, 1);
        PV_QTR(0, cB, 2, 3);
        PV_QTR(4, cB, 2, 3);

        BAR_GRP(barid);        // group done reading this slot
        if (t + 8 < NTILES)
            prefetch_tile(kv, t + 8, lt);   // refill the slot just consumed
        CP_COMMIT();           // keep wait_group counting uniform
    }

    // rs: full row sums (already reduced across lanes by the MMA)
    float rs[4] = {os0[0], os0[2], os1[0], os1[2]};

    // ---- combine the four groups (reuse KV smem as scratch) ----
    __syncthreads();
    float* sc = (float*)(sm + SM_KV);     // 3 x 64 threads x 68 floats
    if (grp > 0) {
        float* d = sc + ((grp - 1) * 64 + lt) * 68;
        #pragma unroll
        for (int nt = 0; nt < 8; nt++) {
            #pragma unroll
            for (int j = 0; j < 4; j++) {
                d[nt * 4 + j]      = o0[nt][j];
                d[32 + nt * 4 + j] = o1[nt][j];
            }
        }
        d[64] = rs[0]; d[65] = rs[1]; d[66] = rs[2]; d[67] = rs[3];
    }
    __syncthreads();
    if (grp == 0) {
        #pragma unroll
        for (int g = 0; g < 3; g++) {
            const float* d = sc + (g * 64 + lt) * 68;
            #pragma unroll
            for (int nt = 0; nt < 8; nt++) {
                #pragma unroll
                for (int j = 0; j < 4; j++) {
                    o0[nt][j] += d[nt * 4 + j];
                    o1[nt][j] += d[32 + nt * 4 + j];
                }
            }
            rs[0] += d[64]; rs[1] += d[65]; rs[2] += d[66]; rs[3] += d[67];
        }

        const float inv[4] = {1.f / rs[0], 1.f / rs[1], 1.f / rs[2], 1.f / rs[3]};

        const int r0 = lane >> 2;
        const int c0 = (lane & 3) * 2;
        #pragma unroll
        for (int m = 0; m < 2; m++) {
            const int mrow = m0 + wg * 32 + m * 16 + r0;
            const float ia = inv[m * 2], ib = inv[m * 2 + 1];
            #pragma unroll
            for (int nt = 0; nt < 8; nt++) {
                const float* oo = m ? o1[nt] : o0[nt];
                float2 v0 = make_float2(oo[0] * ia, oo[1] * ia);
                float2 v1 = make_float2(oo[2] * ib, oo[3] * ib);
                *(float2*)(out + (size_t)mrow * 64 + nt * 8 + c0)       = v0;
                *(float2*)(out + (size_t)(mrow + 8) * 64 + nt * 8 + c0) = v1;
            }
        }
    }
}

// ===========================================================================
extern "C" void kernel_launch(void* const* d_in, const int* in_sizes, int n_in,
                              void* d_out, int out_size)
{
    const float* hid = (const float*)d_in[0];
    const float* wq  = (const float*)d_in[1];
    const float* wk  = (const float*)d_in[2];
    const float* wv  = (const float*)d_in[3];
    float* out = (float*)d_out;

    cudaFuncSetAttribute(qkv_kernel,
                         cudaFuncAttributeMaxDynamicSharedMemorySize, QKV_SMEM);
    cudaFuncSetAttribute(attn_mma,
                         cudaFuncAttributeMaxDynamicSharedMemorySize, SMEM_TOTAL);

    qkv_kernel<<<N_TOK / 64, 512, QKV_SMEM>>>(hid, wq, wk, wv);
    attn_mma<<<N_TOK / BM, 256, SMEM_TOTAL>>>(out);
}

// round 14
// speedup vs baseline: 1.1909x; 1.1486x over previous
#include <cuda_runtime.h>
#include <cuda_fp16.h>
#include <cstdint>
#include <math.h>

#define N_TOK 8192
#define C_DIM 128
#define D_DIM 64

#define BM 64
#define BN 64
#define NTILES (N_TOK / BN)

// ===========================================================================
// Globals (allocation-free scratch), all fp16
// ===========================================================================
__device__ __half g_q [N_TOK * D_DIM];   // [n][d], pre-scaled by log2e/8
__device__ __half g_k [N_TOK * D_DIM];   // [n][d]
__device__ __half g_vT[D_DIM * N_TOK];   // [d][n]
__device__ __half g_wT[3 * 64 * 128];    // [m][o][c] fp16; wq pre-scaled

// ===========================================================================
// PTX helpers (base-ISA only)
// ===========================================================================
__device__ __forceinline__ uint32_t smem_u32(const void* p) {
    uint32_t a;
    asm("{ .reg .u64 t; cvta.to.shared.u64 t, %1; cvt.u32.u64 %0, t; }"
        : "=r"(a) : "l"(p));
    return a;
}
#define CP16(dst, src) \
    asm volatile("cp.async.cg.shared.global [%0], [%1], 16;" \
        :: "r"(dst), "l"(src))
#define CP_COMMIT() asm volatile("cp.async.commit_group;")
#define CP_WAIT1()  asm volatile("cp.async.wait_group 1;" ::: "memory")
#define CP_WAIT0()  asm volatile("cp.async.wait_group 0;" ::: "memory")
#define BAR_GRP(id) \
    asm volatile("bar.sync %0, 64;" :: "r"(id) : "memory")

#define LDSM4(r, addr) \
    asm volatile("ldmatrix.sync.aligned.m8n8.x4.shared.b16 {%0,%1,%2,%3}, [%4];" \
        : "=r"((r)[0]), "=r"((r)[1]), "=r"((r)[2]), "=r"((r)[3]) : "r"(addr))

__device__ __forceinline__ void mma16816(float d[4], const uint32_t a[4],
                                         const uint32_t b[2]) {
    asm volatile(
        "mma.sync.aligned.m16n8k16.row.col.f32.f16.f16.f32 "
        "{%0,%1,%2,%3}, {%4,%5,%6,%7}, {%8,%9}, {%0,%1,%2,%3};"
        : "+f"(d[0]), "+f"(d[1]), "+f"(d[2]), "+f"(d[3])
        : "r"(a[0]), "r"(a[1]), "r"(a[2]), "r"(a[3]), "r"(b[0]), "r"(b[1]));
}

// packs: result.lo = f16(a), result.hi = f16(b)
#define CVT_F16X2(result, a, b) \
    asm("cvt.rn.f16x2.f32 %0, %1, %2;" : "=r"(result) : "f"(b), "f"(a))
// packed fp16x2 exp2 (scores pre-scaled by log2e)
#define HEX2(r, x) asm("ex2.approx.f16x2 %0, %1;" : "=r"(r) : "r"(x))

// ===========================================================================
// Kernel 0: W transpose + fp16 convert (q scale folded)
// ===========================================================================
__global__ void prep_w(const float* __restrict__ wq,
                       const float* __restrict__ wk,
                       const float* __restrict__ wv)
{
    int idx = blockIdx.x * 256 + threadIdx.x;   // over [c][o], 8192
    int c = idx >> 6, o = idx & 63;
    g_wT[0 * 8192 + o * 128 + c] = __float2half(wq[idx] * 0.1803368801f);
    g_wT[1 * 8192 + o * 128 + c] = __float2half(wk[idx]);
    g_wT[2 * 8192 + o * 128 + c] = __float2half(wv[idx]);
}

// ===========================================================================
// Kernel 1: tensor-core QKV. 128 blocks x 256 threads, 64 tokens/block.
// Warps 0-3: Q + V cols 0-31. Warps 4-7: K + V cols 32-63.
// smem: x lo/hi (2 x 8KB) | W tiles (3 x 16KB) | v staging (9KB)
// ===========================================================================
#define QT_XLO 0
#define QT_XHI 8192
#define QT_W   16384
#define QT_VS  65536
#define QT_SMEM (QT_VS + 64 * 72 * 2)     // 74752 bytes

__global__ __launch_bounds__(256) void qkv_tc(const float* __restrict__ hid)
{
    extern __shared__ char sm[];
    const uint32_t sb = smem_u32(sm);
    const int tid  = threadIdx.x;
    const int lane = tid & 31;
    const int w    = tid >> 5;
    const int n0   = blockIdx.x * 64;
    const int bt   = n0 >> 8;
    const int hw0  = n0 & 255;
    const float* base = hid + (size_t)bt * (C_DIM * 256) + hw0;

    // stage W (6 tiles of 8KB) via cp.async, swizzled
    #pragma unroll
    for (int i = 0; i < 12; i++) {
        int id = tid + i * 256;               // 0..3071 16B chunks
        int t  = id >> 9;                     // tile 0..5 = (m, c-half)
        int rem = id & 511;
        int o = rem >> 3, ch = (rem & 7) * 16;
        int m = t >> 1, hf = t & 1;
        uint32_t sw = (uint32_t)o * 128 + (uint32_t)(ch ^ ((o & 7) << 4));
        CP16(sb + QT_W + t * 8192 + sw,
             (const char*)g_wT + m * 16384 + o * 256 + hf * 128 + ch);
    }
    CP_COMMIT();

    // gather x (fp32, coalesced over tokens) -> fp16x2 -> swizzled smem
    #pragma unroll
    for (int i = 0; i < 16; i++) {
        int idx = tid + i * 256;              // over [c2][r], 4096
        int r = idx & 63, c2 = idx >> 6;      // c2: fp16x2 column pair
        float f0 = base[(2 * c2)     * 256 + r];
        float f1 = base[(2 * c2 + 1) * 256 + r];
        __half2 h = __floats2half2_rn(f0, f1);
        uint32_t tile = (c2 < 32) ? QT_XLO : QT_XHI;
        uint32_t boff = (uint32_t)r * 128
                      + (uint32_t)(((c2 & 31) * 4) ^ ((r & 7) << 4));
        *(__half2*)(sm + tile + boff) = h;
    }
    CP_WAIT0();
    __syncthreads();

    // A-fragments: 8 k-steps, rows r0..r0+15
    const int r0 = (w & 3) * 16;
    uint32_t af[8][4];
    {
        uint32_t cxor = (uint32_t)(lane & 7) << 4;
        uint32_t rowb = sb + (uint32_t)(r0 + (lane & 15)) * 128;
        #pragma unroll
        for (int ks = 0; ks < 8; ks++) {
            uint32_t tile = (ks < 4) ? QT_XLO : QT_XHI;
            uint32_t ch = (uint32_t)((ks & 3) * 32 + ((lane >> 4) << 4));
            LDSM4(af[ks], rowb + tile + (ch ^ cxor));
        }
    }

    const uint32_t browB = (uint32_t)(lane & 7) * 128;
    const uint32_t cA = (uint32_t)((((lane >> 3) & 3) << 4) ^ ((lane & 7) << 4));
    const uint32_t cB = cA ^ 64u;

    // GEMM 1: q (warps 0-3) or k (warps 4-7)
    float oq[8][4];
    #pragma unroll
    for (int nb = 0; nb < 8; nb++)
        #pragma unroll
        for (int j = 0; j < 4; j++) oq[nb][j] = 0.f;
    {
        uint32_t wbase = sb + QT_W + ((w < 4) ? 0 : 16384);
        #pragma unroll
        for (int nb = 0; nb < 8; nb++) {
            uint32_t rl = wbase + (uint32_t)nb * 1024 + browB;
            uint32_t rh = rl + 8192;
            uint32_t b01[4], b23[4], b45[4], b67[4];
            LDSM4(b01, rl + cA); LDSM4(b23, rl + cB);
            LDSM4(b45, rh + cA); LDSM4(b67, rh + cB);
            mma16816(oq[nb], af[0], b01 + 0); mma16816(oq[nb], af[1], b01 + 2);
            mma16816(oq[nb], af[2], b23 + 0); mma16816(oq[nb], af[3], b23 + 2);
            mma16816(oq[nb], af[4], b45 + 0); mma16816(oq[nb], af[5], b45 + 2);
            mma16816(oq[nb], af[6], b67 + 0); mma16816(oq[nb], af[7], b67 + 2);
        }
    }
    // GEMM 2: v, n-half per warp group
    float ov[4][4];
    #pragma unroll
    for (int j = 0; j < 4; j++)
        #pragma unroll
        for (int c = 0; c < 4; c++) ov[j][c] = 0.f;
    const int nb0 = (w < 4) ? 0 : 4;
    {
        uint32_t vbase = sb + QT_W + 32768;
        #pragma unroll
        for (int j = 0; j < 4; j++) {
            uint32_t rl = vbase + (uint32_t)(nb0 + j) * 1024 + browB;
            uint32_t rh = rl + 8192;
            uint32_t b01[4], b23[4], b45[4], b67[4];
            LDSM4(b01, rl + cA); LDSM4(b23, rl + cB);
            LDSM4(b45, rh + cA); LDSM4(b67, rh + cB);
            mma16816(ov[j], af[0], b01 + 0); mma16816(ov[j], af[1], b01 + 2);
            mma16816(ov[j], af[2], b23 + 0); mma16816(ov[j], af[3], b23 + 2);
            mma16816(ov[j], af[4], b45 + 0); mma16816(ov[j], af[5], b45 + 2);
            mma16816(ov[j], af[6], b67 + 0); mma16816(ov[j], af[7], b67 + 2);
        }
    }

    // store q/k directly (fp16)
    {
        __half* dst = (w < 4) ? g_q : g_k;
        const int row = r0 + (lane >> 2);
        const int c0  = (lane & 3) * 2;
        #pragma unroll
        for (int nb = 0; nb < 8; nb++) {
            *(__half2*)(dst + (size_t)(n0 + row) * 64 + nb * 8 + c0)
                = __floats2half2_rn(oq[nb][0], oq[nb][1]);
            *(__half2*)(dst + (size_t)(n0 + row + 8) * 64 + nb * 8 + c0)
                = __floats2half2_rn(oq[nb][2], oq[nb][3]);
        }
    }
    // v -> padded smem [d][72 tokens] for coalesced transpose-out
    {
        __half* vsh = (__half*)(sm + QT_VS);
        const int row = r0 + (lane >> 2);
        const int c0  = (lane & 3) * 2;
        #pragma unroll
        for (int j = 0; j < 4; j++) {
            int col = (nb0 + j) * 8 + c0;
            vsh[(col    ) * 72 + row    ] = __float2half(ov[j][0]);
            vsh[(col + 1) * 72 + row    ] = __float2half(ov[j][1]);
            vsh[(col    ) * 72 + row + 8] = __float2half(ov[j][2]);
            vsh[(col + 1) * 72 + row + 8] = __float2half(ov[j][3]);
        }
    }
    __syncthreads();
    {
        __half* vsh = (__half*)(sm + QT_VS);
        #pragma unroll
        for (int i = 0; i < 2; i++) {
            int id = tid + i * 256;
            int d = id >> 3, ch = id & 7;
            uint4 u = *(uint4*)&vsh[d * 72 + ch * 8];
            *(uint4*)((char*)g_vT + (size_t)d * 16384 + n0 * 2 + ch * 16) = u;
        }
    }
}

// ===========================================================================
// Kernel 2: flash attention (unchanged from R13 best).
// ===========================================================================
#define SM_Q   0
#define SM_KV  8192
#define KVBUF  16384            // k 0 | v 8192
#define SMEM_TOTAL (SM_KV + 8 * KVBUF)    // 139264 bytes

__device__ __forceinline__ void prefetch_tile(uint32_t kvbuf, int t, int lt)
{
    #pragma unroll
    for (int i = 0; i < 8; i++) {
        int id = lt + i * 64;
        int row = id >> 3;
        int ch  = (id & 7) * 16;
        uint32_t sw = (uint32_t)row * 128 + (uint32_t)(ch ^ ((row & 7) << 4));
        CP16(kvbuf +         sw, (const char*)g_k  + t * 8192 + row * 128 + ch);
        CP16(kvbuf + 8192 + sw, (const char*)g_vT + (size_t)row * 16384 + t * 128 + ch);
    }
}

#define SOFTMAX_ONE(S, PHI, nt) do {                                          \
    uint32_t p01, p23;                                                        \
    CVT_F16X2(p01, S[nt][0], S[nt][1]);                                       \
    CVT_F16X2(p23, S[nt][2], S[nt][3]);                                       \
    const int kk = (nt) >> 1, u = ((nt) & 1) * 2;                             \
    HEX2(PHI[kk][u],     p01);                                                \
    HEX2(PHI[kk][u + 1], p23);                                                \
} while (0)

#define S_HALF(base) do {                                                     \
    uint32_t B[4][8];                                                         \
    _Pragma("unroll")                                                         \
    for (int j = 0; j < 4; j++) {                                             \
        uint32_t rb = kv + (uint32_t)((base) + j) * 1024 + browB;             \
        LDSM4(&B[j][0], rb + cA);                                             \
        LDSM4(&B[j][4], rb + cB);                                             \
    }                                                                         \
    _Pragma("unroll")                                                         \
    for (int ks = 0; ks < 4; ks++)                                            \
        _Pragma("unroll")                                                     \
        for (int j = 0; j < 4; j++) {                                         \
            mma16816(s0[(base) + j], qf[0][ks], &B[j][ks * 2]);               \
            mma16816(s1[(base) + j], qf[1][ks], &B[j][ks * 2]);               \
        }                                                                     \
} while (0)

#define PV_QTR(base, COFF, PA, PB) do {                                       \
    uint32_t B[4][4];                                                         \
    _Pragma("unroll")                                                         \
    for (int j = 0; j < 4; j++) {                                             \
        uint32_t rb = kv + 8192 + (uint32_t)((base) + j) * 1024 + browB;      \
        LDSM4(&B[j][0], rb + (COFF));                                         \
    }                                                                         \
    _Pragma("unroll")                                                         \
    for (int j = 0; j < 4; j++) {                                             \
        mma16816(o0[(base) + j], phi0[PA], &B[j][0]);                         \
        mma16816(o1[(base) + j], phi1[PA], &B[j][0]);                         \
    }                                                                         \
    _Pragma("unroll")                                                         \
    for (int j = 0; j < 4; j++) {                                             \
        mma16816(o0[(base) + j], phi0[PB], &B[j][2]);                         \
        mma16816(o1[(base) + j], phi1[PB], &B[j][2]);                         \
    }                                                                         \
} while (0)

__global__ __launch_bounds__(256, 1) void attn_mma(float* __restrict__ out)
{
    extern __shared__ char sm[];
    const uint32_t sb = smem_u32(sm);
    const int tid  = threadIdx.x;
    const int lane = tid & 31;
    const int wid  = tid >> 5;        // 0..7
    const int grp  = wid >> 1;        // 0..3: tiles t = grp mod 4
    const int wg   = wid & 1;         // warp-in-group: rows wg*32..wg*32+31
    const int lt   = tid & 63;        // thread id within group
    const int m0   = blockIdx.x * BM;

    // ---- stage Q tile (swizzled), all 256 threads ----
    {
        const char* qg = (const char*)g_q + m0 * 128;   // 64 rows x 128B
        int row = tid >> 2;
        int ch  = (tid & 3) * 32;      // 2 x 16B per thread
        uint32_t sw0 = (uint32_t)row * 128 + (uint32_t)((ch)      ^ ((row & 7) << 4));
        uint32_t sw1 = (uint32_t)row * 128 + (uint32_t)((ch + 16) ^ ((row & 7) << 4));
        *(uint4*)(sm + SM_Q + sw0) = *(const uint4*)(qg + row * 128 + ch);
        *(uint4*)(sm + SM_Q + sw1) = *(const uint4*)(qg + row * 128 + ch + 16);
    }

    // prologue: each group prefetches its first two tiles into its 2 slots
    const uint32_t ring = sb + SM_KV + (uint32_t)grp * 2 * KVBUF;
    prefetch_tile(ring,         grp,     lt);
    CP_COMMIT();
    prefetch_tile(ring + KVBUF, grp + 4, lt);
    CP_COMMIT();
    __syncthreads();

    // ---- Q A-fragments: 2 m-fragments (32 rows) per warp ----
    uint32_t qf[2][4][4];
    {
        uint32_t cxor = (uint32_t)(lane & 7) << 4;
        #pragma unroll
        for (int m = 0; m < 2; m++) {
            int qrow = wg * 32 + m * 16 + (lane & 15);
            uint32_t qbase = sb + SM_Q + (uint32_t)qrow * 128;
            #pragma unroll
            for (int ks = 0; ks < 4; ks++) {
                uint32_t ch = (uint32_t)(ks * 32 + ((lane >> 4) << 4));
                LDSM4(qf[m][ks], qbase + (ch ^ cxor));
            }
        }
    }

    float o0[8][4], o1[8][4];
    #pragma unroll
    for (int nt = 0; nt < 8; nt++)
        #pragma unroll
        for (int j = 0; j < 4; j++) { o0[nt][j] = 0.f; o1[nt][j] = 0.f; }
    float os0[4] = {0.f, 0.f, 0.f, 0.f};
    float os1[4] = {0.f, 0.f, 0.f, 0.f};
    const uint32_t onesb[2] = {0x3C003C00u, 0x3C003C00u};   // fp16 1.0 x4

    const uint32_t browB = (uint32_t)(lane & 7) * 128;
    const uint32_t cA = (uint32_t)((((lane >> 3) & 3) << 4) ^ ((lane & 7) << 4));
    const uint32_t cB = cA ^ 64u;
    const int barid = grp + 1;

    int slot = 0;
    for (int t = grp; t < NTILES; t += 4, slot ^= 1) {
        const uint32_t kv = ring + (uint32_t)slot * KVBUF;

        CP_WAIT1();
        BAR_GRP(barid);

        float s0[8][4], s1[8][4];
        #pragma unroll
        for (int nt = 0; nt < 8; nt++)
            #pragma unroll
            for (int j = 0; j < 4; j++) { s0[nt][j] = 0.f; s1[nt][j] = 0.f; }

        uint32_t phi0[4][4], phi1[4][4];

        S_HALF(0);
        S_HALF(4);
        SOFTMAX_ONE(s0, phi0, 0); SOFTMAX_ONE(s1, phi1, 0);
        SOFTMAX_ONE(s0, phi0, 1); SOFTMAX_ONE(s1, phi1, 1);
        SOFTMAX_ONE(s0, phi0, 2); SOFTMAX_ONE(s1, phi1, 2);
        SOFTMAX_ONE(s0, phi0, 3); SOFTMAX_ONE(s1, phi1, 3);
        mma16816(os0, phi0[0], onesb); mma16816(os1, phi1[0], onesb);
        mma16816(os0, phi0[1], onesb); mma16816(os1, phi1[1], onesb);
        PV_QTR(0, cA, 0, 1);
        SOFTMAX_ONE(s0, phi0, 4); SOFTMAX_ONE(s1, phi1, 4);
        SOFTMAX_ONE(s0, phi0, 5); SOFTMAX_ONE(s1, phi1, 5);
        SOFTMAX_ONE(s0, phi0, 6); SOFTMAX_ONE(s1, phi1, 6);
        SOFTMAX_ONE(s0, phi0, 7); SOFTMAX_ONE(s1, phi1, 7);
        mma16816(os0, phi0[2], onesb); mma16816(os1, phi1[2], onesb);
        mma16816(os0, phi0[3], onesb); mma16816(os1, phi1[3], onesb);
        PV_QTR(4, cA, 0, 1);
        PV_QTR(0, cB, 2, 3);
        PV_QTR(4, cB, 2, 3);

        BAR_GRP(barid);
        if (t + 8 < NTILES)
            prefetch_tile(kv, t + 8, lt);
        CP_COMMIT();
    }

    float rs[4] = {os0[0], os0[2], os1[0], os1[2]};

    __syncthreads();
    float* sc = (float*)(sm + SM_KV);
    if (grp > 0) {
        float* d = sc + ((grp - 1) * 64 + lt) * 68;
        #pragma unroll
        for (int nt = 0; nt < 8; nt++) {
            #pragma unroll
            for (int j = 0; j < 4; j++) {
                d[nt * 4 + j]      = o0[nt][j];
                d[32 + nt * 4 + j] = o1[nt][j];
            }
        }
        d[64] = rs[0]; d[65] = rs[1]; d[66] = rs[2]; d[67] = rs[3];
    }
    __syncthreads();
    if (grp == 0) {
        #pragma unroll
        for (int g = 0; g < 3; g++) {
            const float* d = sc + (g * 64 + lt) * 68;
            #pragma unroll
            for (int nt = 0; nt < 8; nt++) {
                #pragma unroll
                for (int j = 0; j < 4; j++) {
                    o0[nt][j] += d[nt * 4 + j];
                    o1[nt][j] += d[32 + nt * 4 + j];
                }
            }
            rs[0] += d[64]; rs[1] += d[65]; rs[2] += d[66]; rs[3] += d[67];
        }

        const float inv[4] = {1.f / rs[0], 1.f / rs[1], 1.f / rs[2], 1.f / rs[3]};

        const int r0 = lane >> 2;
        const int c0 = (lane & 3) * 2;
        #pragma unroll
        for (int m = 0; m < 2; m++) {
            const int mrow = m0 + wg * 32 + m * 16 + r0;
            const float ia = inv[m * 2], ib = inv[m * 2 + 1];
            #pragma unroll
            for (int nt = 0; nt < 8; nt++) {
                const float* oo = m ? o1[nt] : o0[nt];
                float2 v0 = make_float2(oo[0] * ia, oo[1] * ia);
                float2 v1 = make_float2(oo[2] * ib, oo[3] * ib);
                *(float2*)(out + (size_t)mrow * 64 + nt * 8 + c0)       = v0;
                *(float2*)(out + (size_t)(mrow + 8) * 64 + nt * 8 + c0) = v1;
            }
        }
    }
}

// ===========================================================================
extern "C" void kernel_launch(void* const* d_in, const int* in_sizes, int n_in,
                              void* d_out, int out_size)
{
    const float* hid = (const float*)d_in[0];
    const float* wq  = (const float*)d_in[1];
    const float* wk  = (const float*)d_in[2];
    const float* wv  = (const float*)d_in[3];
    float* out = (float*)d_out;

    cudaFuncSetAttribute(qkv_tc,
                         cudaFuncAttributeMaxDynamicSharedMemorySize, QT_SMEM);
    cudaFuncSetAttribute(attn_mma,
                         cudaFuncAttributeMaxDynamicSharedMemorySize, SMEM_TOTAL);

    prep_w<<<32, 256>>>(wq, wk, wv);
    qkv_tc<<<N_TOK / 64, 256, QT_SMEM>>>(hid);
    attn_mma<<<N_TOK / BM, 256, SMEM_TOTAL>>>(out);
}

// round 15
// speedup vs baseline: 1.2205x; 1.0249x over previous
#include <cuda_runtime.h>
#include <cuda_fp16.h>
#include <cstdint>
#include <math.h>

#define N_TOK 8192
#define C_DIM 128
#define D_DIM 64

#define BM 64
#define BN 64
#define NTILES (N_TOK / BN)

// ===========================================================================
// Globals (allocation-free scratch), all fp16
// ===========================================================================
__device__ __half g_q [N_TOK * D_DIM];   // [n][d], pre-scaled by log2e/8
__device__ __half g_k [N_TOK * D_DIM];   // [n][d]
__device__ __half g_vT[D_DIM * N_TOK];   // [d][n]

// ===========================================================================
// PTX helpers (base-ISA only)
// ===========================================================================
__device__ __forceinline__ uint32_t smem_u32(const void* p) {
    uint32_t a;
    asm("{ .reg .u64 t; cvta.to.shared.u64 t, %1; cvt.u32.u64 %0, t; }"
        : "=r"(a) : "l"(p));
    return a;
}
#define CP16(dst, src) \
    asm volatile("cp.async.cg.shared.global [%0], [%1], 16;" \
        :: "r"(dst), "l"(src))
#define CP_COMMIT() asm volatile("cp.async.commit_group;")
#define CP_WAIT1()  asm volatile("cp.async.wait_group 1;" ::: "memory")
#define BAR_GRP(id) \
    asm volatile("bar.sync %0, 64;" :: "r"(id) : "memory")

#define LDSM4(r, addr) \
    asm volatile("ldmatrix.sync.aligned.m8n8.x4.shared.b16 {%0,%1,%2,%3}, [%4];" \
        : "=r"((r)[0]), "=r"((r)[1]), "=r"((r)[2]), "=r"((r)[3]) : "r"(addr))

__device__ __forceinline__ void mma16816(float d[4], const uint32_t a[4],
                                         const uint32_t b[2]) {
    asm volatile(
        "mma.sync.aligned.m16n8k16.row.col.f32.f16.f16.f32 "
        "{%0,%1,%2,%3}, {%4,%5,%6,%7}, {%8,%9}, {%0,%1,%2,%3};"
        : "+f"(d[0]), "+f"(d[1]), "+f"(d[2]), "+f"(d[3])
        : "r"(a[0]), "r"(a[1]), "r"(a[2]), "r"(a[3]), "r"(b[0]), "r"(b[1]));
}

// packs: result.lo = f16(a), result.hi = f16(b)
#define CVT_F16X2(result, a, b) \
    asm("cvt.rn.f16x2.f32 %0, %1, %2;" : "=r"(result) : "f"(b), "f"(a))
// packed fp16x2 exp2 (scores pre-scaled by log2e)
#define HEX2(r, x) asm("ex2.approx.f16x2 %0, %1;" : "=r"(r) : "r"(x))

// ===========================================================================
// Kernel 1: tensor-core QKV (W converted in-kernel; no prep pass).
// 128 blocks x 256 threads, 64 tokens/block.
// Warps 0-3: Q + V cols 0-31. Warps 4-7: K + V cols 32-63.
// smem: x lo/hi (2 x 8KB) | W tiles (3 x 16KB) | v staging (9KB)
// ===========================================================================
#define QT_XLO 0
#define QT_XHI 8192
#define QT_W   16384
#define QT_VS  65536
#define QT_SMEM (QT_VS + 64 * 72 * 2)     // 74752 bytes

__global__ __launch_bounds__(256) void qkv_tc(
    const float* __restrict__ hid,
    const float* __restrict__ wq,
    const float* __restrict__ wk,
    const float* __restrict__ wv)
{
    extern __shared__ char sm[];
    const uint32_t sb = smem_u32(sm);
    const int tid  = threadIdx.x;
    const int lane = tid & 31;
    const int w    = tid >> 5;
    const int n0   = blockIdx.x * 64;
    const int bt   = n0 >> 8;
    const int hw0  = n0 & 255;
    const float* base = hid + (size_t)bt * (C_DIM * 256) + hw0;

    // stage W: load fp32 [c][o] (coalesced over o, L2-hit), convert, store
    // swizzled [o][c] fp16 into 6 tiles of 8KB (tile = m*2 + c-half)
    #pragma unroll
    for (int m = 0; m < 3; m++) {
        const float* wm = (m == 0) ? wq : (m == 1) ? wk : wv;
        const float sc = (m == 0) ? 0.1803368801f : 1.0f;   // /8 * log2e
        #pragma unroll
        for (int i = 0; i < 16; i++) {
            int id = tid + i * 256;          // (c2, o): 4096
            int o  = id & 63;
            int c2 = id >> 6;                // 0..63 column pairs
            float f0 = __ldg(wm + (2 * c2)     * 64 + o) * sc;
            float f1 = __ldg(wm + (2 * c2 + 1) * 64 + o) * sc;
            uint32_t h;
            CVT_F16X2(h, f0, f1);
            uint32_t tile = QT_W + (uint32_t)(m * 2 + (c2 >> 5)) * 8192;
            uint32_t off = (uint32_t)o * 128
                         + (uint32_t)(((c2 & 31) * 4) ^ ((o & 7) << 4));
            *(uint32_t*)(sm + tile + off) = h;
        }
    }

    // gather x (fp32, coalesced over tokens) -> fp16x2 -> swizzled smem
    #pragma unroll
    for (int i = 0; i < 16; i++) {
        int idx = tid + i * 256;              // over [c2][r], 4096
        int r = idx & 63, c2 = idx >> 6;      // c2: fp16x2 column pair
        float f0 = base[(2 * c2)     * 256 + r];
        float f1 = base[(2 * c2 + 1) * 256 + r];
        __half2 h = __floats2half2_rn(f0, f1);
        uint32_t tile = (c2 < 32) ? QT_XLO : QT_XHI;
        uint32_t boff = (uint32_t)r * 128
                      + (uint32_t)(((c2 & 31) * 4) ^ ((r & 7) << 4));
        *(__half2*)(sm + tile + boff) = h;
    }
    __syncthreads();

    // A-fragments: 8 k-steps, rows r0..r0+15
    const int r0 = (w & 3) * 16;
    uint32_t af[8][4];
    {
        uint32_t cxor = (uint32_t)(lane & 7) << 4;
        uint32_t rowb = sb + (uint32_t)(r0 + (lane & 15)) * 128;
        #pragma unroll
        for (int ks = 0; ks < 8; ks++) {
            uint32_t tile = (ks < 4) ? QT_XLO : QT_XHI;
            uint32_t ch = (uint32_t)((ks & 3) * 32 + ((lane >> 4) << 4));
            LDSM4(af[ks], rowb + tile + (ch ^ cxor));
        }
    }

    const uint32_t browB = (uint32_t)(lane & 7) * 128;
    const uint32_t cA = (uint32_t)((((lane >> 3) & 3) << 4) ^ ((lane & 7) << 4));
    const uint32_t cB = cA ^ 64u;

    // GEMM 1: q (warps 0-3) or k (warps 4-7)
    float oq[8][4];
    #pragma unroll
    for (int nb = 0; nb < 8; nb++)
        #pragma unroll
        for (int j = 0; j < 4; j++) oq[nb][j] = 0.f;
    {
        uint32_t wbase = sb + QT_W + ((w < 4) ? 0 : 16384);
        #pragma unroll
        for (int nb = 0; nb < 8; nb++) {
            uint32_t rl = wbase + (uint32_t)nb * 1024 + browB;
            uint32_t rh = rl + 8192;
            uint32_t b01[4], b23[4], b45[4], b67[4];
            LDSM4(b01, rl + cA); LDSM4(b23, rl + cB);
            LDSM4(b45, rh + cA); LDSM4(b67, rh + cB);
            mma16816(oq[nb], af[0], b01 + 0); mma16816(oq[nb], af[1], b01 + 2);
            mma16816(oq[nb], af[2], b23 + 0); mma16816(oq[nb], af[3], b23 + 2);
            mma16816(oq[nb], af[4], b45 + 0); mma16816(oq[nb], af[5], b45 + 2);
            mma16816(oq[nb], af[6], b67 + 0); mma16816(oq[nb], af[7], b67 + 2);
        }
    }
    // GEMM 2: v, n-half per warp group
    float ov[4][4];
    #pragma unroll
    for (int j = 0; j < 4; j++)
        #pragma unroll
        for (int c = 0; c < 4; c++) ov[j][c] = 0.f;
    const int nb0 = (w < 4) ? 0 : 4;
    {
        uint32_t vbase = sb + QT_W + 32768;
        #pragma unroll
        for (int j = 0; j < 4; j++) {
            uint32_t rl = vbase + (uint32_t)(nb0 + j) * 1024 + browB;
            uint32_t rh = rl + 8192;
            uint32_t b01[4], b23[4], b45[4], b67[4];
            LDSM4(b01, rl + cA); LDSM4(b23, rl + cB);
            LDSM4(b45, rh + cA); LDSM4(b67, rh + cB);
            mma16816(ov[j], af[0], b01 + 0); mma16816(ov[j], af[1], b01 + 2);
            mma16816(ov[j], af[2], b23 + 0); mma16816(ov[j], af[3], b23 + 2);
            mma16816(ov[j], af[4], b45 + 0); mma16816(ov[j], af[5], b45 + 2);
            mma16816(ov[j], af[6], b67 + 0); mma16816(ov[j], af[7], b67 + 2);
        }
    }

    // store q/k directly (fp16)
    {
        __half* dst = (w < 4) ? g_q : g_k;
        const int row = r0 + (lane >> 2);
        const int c0  = (lane & 3) * 2;
        #pragma unroll
        for (int nb = 0; nb < 8; nb++) {
            *(__half2*)(dst + (size_t)(n0 + row) * 64 + nb * 8 + c0)
                = __floats2half2_rn(oq[nb][0], oq[nb][1]);
            *(__half2*)(dst + (size_t)(n0 + row + 8) * 64 + nb * 8 + c0)
                = __floats2half2_rn(oq[nb][2], oq[nb][3]);
        }
    }
    // v -> padded smem [d][72 tokens] for coalesced transpose-out
    {
        __half* vsh = (__half*)(sm + QT_VS);
        const int row = r0 + (lane >> 2);
        const int c0  = (lane & 3) * 2;
        #pragma unroll
        for (int j = 0; j < 4; j++) {
            int col = (nb0 + j) * 8 + c0;
            vsh[(col    ) * 72 + row    ] = __float2half(ov[j][0]);
            vsh[(col + 1) * 72 + row    ] = __float2half(ov[j][1]);
            vsh[(col    ) * 72 + row + 8] = __float2half(ov[j][2]);
            vsh[(col + 1) * 72 + row + 8] = __float2half(ov[j][3]);
        }
    }
    __syncthreads();
    {
        __half* vsh = (__half*)(sm + QT_VS);
        #pragma unroll
        for (int i = 0; i < 2; i++) {
            int id = tid + i * 256;
            int d = id >> 3, ch = id & 7;
            uint4 u = *(uint4*)&vsh[d * 72 + ch * 8];
            *(uint4*)((char*)g_vT + (size_t)d * 16384 + n0 * 2 + ch * 16) = u;
        }
    }
}

// ===========================================================================
// Kernel 2: flash attention (unchanged from R13/R14 best).
// ===========================================================================
#define SM_Q   0
#define SM_KV  8192
#define KVBUF  16384            // k 0 | v 8192
#define SMEM_TOTAL (SM_KV + 8 * KVBUF)    // 139264 bytes

__device__ __forceinline__ void prefetch_tile(uint32_t kvbuf, int t, int lt)
{
    #pragma unroll
    for (int i = 0; i < 8; i++) {
        int id = lt + i * 64;
        int row = id >> 3;
        int ch  = (id & 7) * 16;
        uint32_t sw = (uint32_t)row * 128 + (uint32_t)(ch ^ ((row & 7) << 4));
        CP16(kvbuf +         sw, (const char*)g_k  + t * 8192 + row * 128 + ch);
        CP16(kvbuf + 8192 + sw, (const char*)g_vT + (size_t)row * 16384 + t * 128 + ch);
    }
}

#define SOFTMAX_ONE(S, PHI, nt) do {                                          \
    uint32_t p01, p23;                                                        \
    CVT_F16X2(p01, S[nt][0], S[nt][1]);                                       \
    CVT_F16X2(p23, S[nt][2], S[nt][3]);                                       \
    const int kk = (nt) >> 1, u = ((nt) & 1) * 2;                             \
    HEX2(PHI[kk][u],     p01);                                                \
    HEX2(PHI[kk][u + 1], p23);                                                \
} while (0)

#define S_HALF(base) do {                                                     \
    uint32_t B[4][8];                                                         \
    _Pragma("unroll")                                                         \
    for (int j = 0; j < 4; j++) {                                             \
        uint32_t rb = kv + (uint32_t)((base) + j) * 1024 + browB;             \
        LDSM4(&B[j][0], rb + cA);                                             \
        LDSM4(&B[j][4], rb + cB);                                             \
    }                                                                         \
    _Pragma("unroll")                                                         \
    for (int ks = 0; ks < 4; ks++)                                            \
        _Pragma("unroll")                                                     \
        for (int j = 0; j < 4; j++) {                                         \
            mma16816(s0[(base) + j], qf[0][ks], &B[j][ks * 2]);               \
            mma16816(s1[(base) + j], qf[1][ks], &B[j][ks * 2]);               \
        }                                                                     \
} while (0)

#define PV_QTR(base, COFF, PA, PB) do {                                       \
    uint32_t B[4][4];                                                         \
    _Pragma("unroll")                                                         \
    for (int j = 0; j < 4; j++) {                                             \
        uint32_t rb = kv + 8192 + (uint32_t)((base) + j) * 1024 + browB;      \
        LDSM4(&B[j][0], rb + (COFF));                                         \
    }                                                                         \
    _Pragma("unroll")                                                         \
    for (int j = 0; j < 4; j++) {                                             \
        mma16816(o0[(base) + j], phi0[PA], &B[j][0]);                         \
        mma16816(o1[(base) + j], phi1[PA], &B[j][0]);                         \
    }                                                                         \
    _Pragma("unroll")                                                         \
    for (int j = 0; j < 4; j++) {                                             \
        mma16816(o0[(base) + j], phi0[PB], &B[j][2]);                         \
        mma16816(o1[(base) + j], phi1[PB], &B[j][2]);                         \
    }                                                                         \
} while (0)

__global__ __launch_bounds__(256, 1) void attn_mma(float* __restrict__ out)
{
    extern __shared__ char sm[];
    const uint32_t sb = smem_u32(sm);
    const int tid  = threadIdx.x;
    const int lane = tid & 31;
    const int wid  = tid >> 5;        // 0..7
    const int grp  = wid >> 1;        // 0..3: tiles t = grp mod 4
    const int wg   = wid & 1;         // warp-in-group: rows wg*32..wg*32+31
    const int lt   = tid & 63;        // thread id within group
    const int m0   = blockIdx.x * BM;

    // ---- stage Q tile (swizzled), all 256 threads ----
    {
        const char* qg = (const char*)g_q + m0 * 128;   // 64 rows x 128B
        int row = tid >> 2;
        int ch  = (tid & 3) * 32;      // 2 x 16B per thread
        uint32_t sw0 = (uint32_t)row * 128 + (uint32_t)((ch)      ^ ((row & 7) << 4));
        uint32_t sw1 = (uint32_t)row * 128 + (uint32_t)((ch + 16) ^ ((row & 7) << 4));
        *(uint4*)(sm + SM_Q + sw0) = *(const uint4*)(qg + row * 128 + ch);
        *(uint4*)(sm + SM_Q + sw1) = *(const uint4*)(qg + row * 128 + ch + 16);
    }

    // prologue: each group prefetches its first two tiles into its 2 slots
    const uint32_t ring = sb + SM_KV + (uint32_t)grp * 2 * KVBUF;
    prefetch_tile(ring,         grp,     lt);
    CP_COMMIT();
    prefetch_tile(ring + KVBUF, grp + 4, lt);
    CP_COMMIT();
    __syncthreads();

    // ---- Q A-fragments: 2 m-fragments (32 rows) per warp ----
    uint32_t qf[2][4][4];
    {
        uint32_t cxor = (uint32_t)(lane & 7) << 4;
        #pragma unroll
        for (int m = 0; m < 2; m++) {
            int qrow = wg * 32 + m * 16 + (lane & 15);
            uint32_t qbase = sb + SM_Q + (uint32_t)qrow * 128;
            #pragma unroll
            for (int ks = 0; ks < 4; ks++) {
                uint32_t ch = (uint32_t)(ks * 32 + ((lane >> 4) << 4));
                LDSM4(qf[m][ks], qbase + (ch ^ cxor));
            }
        }
    }

    float o0[8][4], o1[8][4];
    #pragma unroll
    for (int nt = 0; nt < 8; nt++)
        #pragma unroll
        for (int j = 0; j < 4; j++) { o0[nt][j] = 0.f; o1[nt][j] = 0.f; }
    float os0[4] = {0.f, 0.f, 0.f, 0.f};
    float os1[4] = {0.f, 0.f, 0.f, 0.f};
    const uint32_t onesb[2] = {0x3C003C00u, 0x3C003C00u};   // fp16 1.0 x4

    const uint32_t browB = (uint32_t)(lane & 7) * 128;
    const uint32_t cA = (uint32_t)((((lane >> 3) & 3) << 4) ^ ((lane & 7) << 4));
    const uint32_t cB = cA ^ 64u;
    const int barid = grp + 1;

    int slot = 0;
    for (int t = grp; t < NTILES; t += 4, slot ^= 1) {
        const uint32_t kv = ring + (uint32_t)slot * KVBUF;

        CP_WAIT1();
        BAR_GRP(barid);

        float s0[8][4], s1[8][4];
        #pragma unroll
        for (int nt = 0; nt < 8; nt++)
            #pragma unroll
            for (int j = 0; j < 4; j++) { s0[nt][j] = 0.f; s1[nt][j] = 0.f; }

        uint32_t phi0[4][4], phi1[4][4];

        S_HALF(0);
        S_HALF(4);
        SOFTMAX_ONE(s0, phi0, 0); SOFTMAX_ONE(s1, phi1, 0);
        SOFTMAX_ONE(s0, phi0, 1); SOFTMAX_ONE(s1, phi1, 1);
        SOFTMAX_ONE(s0, phi0, 2); SOFTMAX_ONE(s1, phi1, 2);
        SOFTMAX_ONE(s0, phi0, 3); SOFTMAX_ONE(s1, phi1, 3);
        mma16816(os0, phi0[0], onesb); mma16816(os1, phi1[0], onesb);
        mma16816(os0, phi0[1], onesb); mma16816(os1, phi1[1], onesb);
        PV_QTR(0, cA, 0, 1);
        SOFTMAX_ONE(s0, phi0, 4); SOFTMAX_ONE(s1, phi1, 4);
        SOFTMAX_ONE(s0, phi0, 5); SOFTMAX_ONE(s1, phi1, 5);
        SOFTMAX_ONE(s0, phi0, 6); SOFTMAX_ONE(s1, phi1, 6);
        SOFTMAX_ONE(s0, phi0, 7); SOFTMAX_ONE(s1, phi1, 7);
        mma16816(os0, phi0[2], onesb); mma16816(os1, phi1[2], onesb);
        mma16816(os0, phi0[3], onesb); mma16816(os1, phi1[3], onesb);
        PV_QTR(4, cA, 0, 1);
        PV_QTR(0, cB, 2, 3);
        PV_QTR(4, cB, 2, 3);

        BAR_GRP(barid);
        if (t + 8 < NTILES)
            prefetch_tile(kv, t + 8, lt);
        CP_COMMIT();
    }

    float rs[4] = {os0[0], os0[2], os1[0], os1[2]};

    __syncthreads();
    float* sc = (float*)(sm + SM_KV);
    if (grp > 0) {
        float* d = sc + ((grp - 1) * 64 + lt) * 68;
        #pragma unroll
        for (int nt = 0; nt < 8; nt++) {
            #pragma unroll
            for (int j = 0; j < 4; j++) {
                d[nt * 4 + j]      = o0[nt][j];
                d[32 + nt * 4 + j] = o1[nt][j];
            }
        }
        d[64] = rs[0]; d[65] = rs[1]; d[66] = rs[2]; d[67] = rs[3];
    }
    __syncthreads();
    if (grp == 0) {
        #pragma unroll
        for (int g = 0; g < 3; g++) {
            const float* d = sc + (g * 64 + lt) * 68;
            #pragma unroll
            for (int nt = 0; nt < 8; nt++) {
                #pragma unroll
                for (int j = 0; j < 4; j++) {
                    o0[nt][j] += d[nt * 4 + j];
                    o1[nt][j] += d[32 + nt * 4 + j];
                }
            }
            rs[0] += d[64]; rs[1] += d[65]; rs[2] += d[66]; rs[3] += d[67];
        }

        const float inv[4] = {1.f / rs[0], 1.f / rs[1], 1.f / rs[2], 1.f / rs[3]};

        const int r0 = lane >> 2;
        const int c0 = (lane & 3) * 2;
        #pragma unroll
        for (int m = 0; m < 2; m++) {
            const int mrow = m0 + wg * 32 + m * 16 + r0;
            const float ia = inv[m * 2], ib = inv[m * 2 + 1];
            #pragma unroll
            for (int nt = 0; nt < 8; nt++) {
                const float* oo = m ? o1[nt] : o0[nt];
                float2 v0 = make_float2(oo[0] * ia, oo[1] * ia);
                float2 v1 = make_float2(oo[2] * ib, oo[3] * ib);
                *(float2*)(out + (size_t)mrow * 64 + nt * 8 + c0)       = v0;
                *(float2*)(out + (size_t)(mrow + 8) * 64 + nt * 8 + c0) = v1;
            }
        }
    }
}

// ===========================================================================
extern "C" void kernel_launch(void* const* d_in, const int* in_sizes, int n_in,
                              void* d_out, int out_size)
{
    const float* hid = (const float*)d_in[0];
    const float* wq  = (const float*)d_in[1];
    const float* wk  = (const float*)d_in[2];
    const float* wv  = (const float*)d_in[3];
    float* out = (float*)d_out;

    cudaFuncSetAttribute(qkv_tc,
                         cudaFuncAttributeMaxDynamicSharedMemorySize, QT_SMEM);
    cudaFuncSetAttribute(attn_mma,
                         cudaFuncAttributeMaxDynamicSharedMemorySize, SMEM_TOTAL);

    qkv_tc<<<N_TOK / 64, 256, QT_SMEM>>>(hid, wq, wk, wv);
    attn_mma<<<N_TOK / BM, 256, SMEM_TOTAL>>>(out);
}